// round 3
// baseline (speedup 1.0000x reference)
#include <cuda_runtime.h>
#include <cuda_bf16.h>

// Fixed shapes
#define HH 96
#define WW 160
#define CC 100
#define hH 48
#define hW 80
#define MD 9
#define KD 19
#define K2 361
#define K2P 364          // padded stride for float4-aligned S rows

// int8 path
#define CP8 112          // channels padded to 112 int8 (7 x 16B chunks)
#define NCH8 7
#define QSCALE 32.0f
#define QSCALE2_INV (1.0f/1024.0f)

// dist-kernel tiling
#define PR 2
#define PC 4
#define TROWS (PR + 2*MD)   // 20
#define TCOLS (PC + 2*MD)   // 22
#define TPITCH 28           // uint4 pitch -> conflict-free 8-lane LDS.128 phases

// scratch (device globals; allocation is forbidden)
__device__ __align__(16) signed char g_xq[hH*hW*CP8];
__device__ __align__(16) signed char g_yq[hH*hW*CP8];
__device__ int g_sxq[hH*hW];
__device__ int g_syq[hH*hW];
__device__ __align__(16) float g_S[hH*hW*K2P];

// ---------------------------------------------------------------------------
// Kernel A: 2x2 avg-pool + int8 quantize (scale 32) + per-pixel sum of squares.
// One warp per (half-res pixel, tensor): 960 blocks for latency hiding.
// ---------------------------------------------------------------------------
__global__ __launch_bounds__(256) void kern_down(const float* __restrict__ prev,
                                                 const float* __restrict__ query) {
    int w    = blockIdx.x * 8 + (threadIdx.x >> 5);
    int lane = threadIdx.x & 31;
    int pixel = w >> 1;
    int tsel  = w & 1;          // 0 -> prev/y, 1 -> query/x
    int r = pixel / hW, c = pixel - r*hW;
    int ch0 = lane * 4;

    const float* src = tsel ? query : prev;
    signed char* dst = tsel ? g_xq : g_yq;
    int* sums        = tsel ? g_sxq : g_syq;

    float4 v = make_float4(0.f,0.f,0.f,0.f);
    if (lane < 25) {            // 25*4 = 100 channels
        int b = ((2*r)*WW + 2*c)*CC + ch0;
        float4 a0 = *(const float4*)&src[b];
        float4 a1 = *(const float4*)&src[b + CC];
        float4 a2 = *(const float4*)&src[b + WW*CC];
        float4 a3 = *(const float4*)&src[b + WW*CC + CC];
        v = make_float4(0.25f*(a0.x+a1.x+a2.x+a3.x), 0.25f*(a0.y+a1.y+a2.y+a3.y),
                        0.25f*(a0.z+a1.z+a2.z+a3.z), 0.25f*(a0.w+a1.w+a2.w+a3.w));
    }
    float vv[4] = {v.x, v.y, v.z, v.w};
    int q[4];
    int s = 0;
    #pragma unroll
    for (int t = 0; t < 4; t++) {
        int a = __float2int_rn(vv[t] * QSCALE);
        a = max(-127, min(127, a));
        q[t] = a;
        s += a*a;
    }
    if (lane < 28) {            // 28*4 = 112 bytes per pixel (pad lanes write zeros)
        char4 cq = make_char4((char)q[0],(char)q[1],(char)q[2],(char)q[3]);
        *(char4*)&dst[pixel*CP8 + ch0] = cq;
    }
    s = __reduce_add_sync(0xffffffffu, s);
    if (lane == 0) sums[pixel] = s;
}

// ---------------------------------------------------------------------------
// Kernel B: local distances via int8 dp4a.  Block = 2x4 pixel tile x 361 k.
// 256 threads: pix = tid&7, kgroup = tid>>3 (32 groups, <=12 k each).
// Two 16B channel chunks staged per sync round; x fully register-resident.
// d = (Sx + Sy - 2*dot)/1024, exact in int32; then (sigmoid(d)-0.5)*2.
// ---------------------------------------------------------------------------
__global__ __launch_bounds__(256) void kern_dist() {
    __shared__ __align__(16) uint4 ysA[TROWS*TPITCH];
    __shared__ __align__(16) uint4 ysB[TROWS*TPITCH];
    __shared__ int sy_s[TROWS*TCOLS];

    int tid = threadIdx.x;
    int pix = tid & 7;
    int kg  = tid >> 3;          // 0..31
    int pr  = pix >> 2, pc = pix & 3;
    int r0 = blockIdx.y * PR, c0 = blockIdx.x * PC;
    int r = r0 + pr, c = c0 + pc;

    int soff[12];
    #pragma unroll
    for (int j = 0; j < 12; j++) {
        int k = kg + 32*j;
        int dy = k / KD;
        int dx = k - dy*KD;
        soff[j] = (pr + dy)*TPITCH + (pc + dx);
    }

    // prefetch all 7 x-chunks into registers
    uint4 xv[NCH8];
    const uint4* xg = reinterpret_cast<const uint4*>(&g_xq[(r*hW + c)*CP8]);
    #pragma unroll
    for (int i = 0; i < NCH8; i++) xv[i] = xg[i];

    int acc[12];
    #pragma unroll
    for (int j = 0; j < 12; j++) acc[j] = 0;

    // rounds over chunk pairs {0,1},{2,3},{4,5}
    #pragma unroll 1
    for (int base = 0; base < 6; base += 2) {
        __syncthreads();
        for (int i = tid; i < TROWS*TCOLS; i += 256) {
            int row = i / TCOLS, col = i - row*TCOLS;
            int gr = r0 - MD + row, gc = c0 - MD + col;
            uint4 va = make_uint4(0u,0u,0u,0u), vb = va;
            if (gr >= 0 && gr < hH && gc >= 0 && gc < hW) {
                const uint4* p = reinterpret_cast<const uint4*>(&g_yq[(gr*hW + gc)*CP8 + base*16]);
                va = p[0]; vb = p[1];
            }
            ysA[row*TPITCH + col] = va;
            ysB[row*TPITCH + col] = vb;
        }
        __syncthreads();

        uint4 xa = xv[base], xb = xv[base+1];
        #pragma unroll
        for (int j = 0; j < 11; j++) {
            uint4 ya = ysA[soff[j]];
            uint4 yb = ysB[soff[j]];
            int a = acc[j];
            a = __dp4a((int)xa.x, (int)ya.x, a);
            a = __dp4a((int)xa.y, (int)ya.y, a);
            a = __dp4a((int)xa.z, (int)ya.z, a);
            a = __dp4a((int)xa.w, (int)ya.w, a);
            a = __dp4a((int)xb.x, (int)yb.x, a);
            a = __dp4a((int)xb.y, (int)yb.y, a);
            a = __dp4a((int)xb.z, (int)yb.z, a);
            a = __dp4a((int)xb.w, (int)yb.w, a);
            acc[j] = a;
        }
        if (kg < 9) {   // j = 11 valid only for k = kg+352 < 361
            uint4 ya = ysA[soff[11]];
            uint4 yb = ysB[soff[11]];
            int a = acc[11];
            a = __dp4a((int)xa.x, (int)ya.x, a);
            a = __dp4a((int)xa.y, (int)ya.y, a);
            a = __dp4a((int)xa.z, (int)ya.z, a);
            a = __dp4a((int)xa.w, (int)ya.w, a);
            a = __dp4a((int)xb.x, (int)yb.x, a);
            a = __dp4a((int)xb.y, (int)yb.y, a);
            a = __dp4a((int)xb.z, (int)yb.z, a);
            a = __dp4a((int)xb.w, (int)yb.w, a);
            acc[11] = a;
        }
    }

    // final chunk (6) + neighbor sum-of-squares staging
    __syncthreads();
    for (int i = tid; i < TROWS*TCOLS; i += 256) {
        int row = i / TCOLS, col = i - row*TCOLS;
        int gr = r0 - MD + row, gc = c0 - MD + col;
        uint4 va = make_uint4(0u,0u,0u,0u);
        int sy = 0;
        if (gr >= 0 && gr < hH && gc >= 0 && gc < hW) {
            va = *reinterpret_cast<const uint4*>(&g_yq[(gr*hW + gc)*CP8 + 6*16]);
            sy = g_syq[gr*hW + gc];
        }
        ysA[row*TPITCH + col] = va;
        sy_s[i] = sy;
    }
    __syncthreads();
    {
        uint4 xa = xv[6];
        #pragma unroll
        for (int j = 0; j < 11; j++) {
            uint4 ya = ysA[soff[j]];
            int a = acc[j];
            a = __dp4a((int)xa.x, (int)ya.x, a);
            a = __dp4a((int)xa.y, (int)ya.y, a);
            a = __dp4a((int)xa.z, (int)ya.z, a);
            a = __dp4a((int)xa.w, (int)ya.w, a);
            acc[j] = a;
        }
        if (kg < 9) {
            uint4 ya = ysA[soff[11]];
            int a = acc[11];
            a = __dp4a((int)xa.x, (int)ya.x, a);
            a = __dp4a((int)xa.y, (int)ya.y, a);
            a = __dp4a((int)xa.z, (int)ya.z, a);
            a = __dp4a((int)xa.w, (int)ya.w, a);
            acc[11] = a;
        }
    }

    int sx = g_sxq[r*hW + c];
    float* Srow = &g_S[(r*hW + c)*K2P];
    #pragma unroll
    for (int j = 0; j < 12; j++) {
        int k = kg + 32*j;
        if (k < K2P) {
            float val = 1.0f;   // PAD / out-of-range -> saturated sigmoid
            if (k < K2) {
                int dy = k / KD, dx = k - dy*KD;
                int sr = r + dy - MD, sc = c + dx - MD;
                if (sr >= 0 && sr < hH && sc >= 0 && sc < hW) {
                    int di = sx + sy_s[(pr + dy)*TCOLS + (pc + dx)] - 2*acc[j];
                    float d = (float)di * QSCALE2_INV;
                    float e = __expf(-d);
                    val = (1.0f - e) / (1.0f + e);   // == (sigmoid(d)-0.5)*2
                }
            }
            Srow[k] = val;
        }
    }
}

// ---------------------------------------------------------------------------
// Kernel C: bilinear upsample (align_corners) + per-object masked min.
// Block = 8 consecutive output pixels (one warp each). Label window staged in
// SMEM with sentinel -1 (covers OOB -> mask false). float4 S loads.
// ---------------------------------------------------------------------------
#define LROWS KD           // 19
#define LCOLS (8 + 2*MD)   // 26
template<int N>
__global__ __launch_bounds__(256) void kern_out(const int* __restrict__ labels,
                                                const int* __restrict__ gt,
                                                float* __restrict__ out) {
    __shared__ int lab[LROWS*LCOLS];
    int tid  = threadIdx.x;
    int warp = tid >> 5;
    int lane = tid & 31;
    int wid = blockIdx.x * 8;          // first pixel of block (same row, WW%8==0)
    int Y = wid / WW;
    int Xbase = wid - Y*WW;

    for (int i = tid; i < LROWS*LCOLS; i += 256) {
        int row = i / LCOLS, col = i - row*LCOLS;
        int gr = Y - MD + row, gc = Xbase - MD + col;
        lab[i] = (gr >= 0 && gr < HH && gc >= 0 && gc < WW) ? labels[gr*WW + gc] : -1;
    }
    __syncthreads();

    int X = Xbase + warp;
    const float sH = (float)(47.0/95.0);
    const float sW = (float)(79.0/159.0);
    float pH = (float)Y * sH;
    float pW = (float)X * sW;
    int loH = (int)floorf(pH); if (loH > hH-2) loH = hH-2;
    int loW = (int)floorf(pW); if (loW > hW-2) loW = hW-2;
    float fH = pH - (float)loH;
    float fW = pW - (float)loW;
    float w00 = (1.f-fH)*(1.f-fW), w01 = (1.f-fH)*fW;
    float w10 = fH*(1.f-fW),       w11 = fH*fW;

    const float* S00 = &g_S[(loH*hW + loW)*K2P];
    const float* S01 = S00 + K2P;
    const float* S10 = S00 + hW*K2P;
    const float* S11 = S10 + K2P;

    int gid[N];
    #pragma unroll
    for (int nn = 0; nn < N; nn++) gid[nn] = gt[nn];
    float mv[N];
    #pragma unroll
    for (int nn = 0; nn < N; nn++) mv[nn] = 1.0f;

    #pragma unroll
    for (int j = 0; j < 3; j++) {
        int kb = 128*j + 4*lane;
        if (kb < K2) {
            float4 a = *(const float4*)&S00[kb];
            float4 b = *(const float4*)&S01[kb];
            float4 cc = *(const float4*)&S10[kb];
            float4 dd = *(const float4*)&S11[kb];
            float av[4] = {a.x,a.y,a.z,a.w};
            float bv[4] = {b.x,b.y,b.z,b.w};
            float cv[4] = {cc.x,cc.y,cc.z,cc.w};
            float dv[4] = {dd.x,dd.y,dd.z,dd.w};
            #pragma unroll
            for (int t = 0; t < 4; t++) {
                int k = kb + t;
                if (k < K2) {
                    int dy = k / KD, dx = k - dy*KD;
                    int lbl = lab[dy*LCOLS + warp + dx];
                    float dval = w00*av[t] + w01*bv[t] + w10*cv[t] + w11*dv[t];
                    #pragma unroll
                    for (int nn = 0; nn < N; nn++)
                        if (lbl == gid[nn]) mv[nn] = fminf(mv[nn], dval);
                }
            }
        }
    }
    #pragma unroll
    for (int nn = 0; nn < N; nn++) {
        float v = mv[nn];
        #pragma unroll
        for (int o = 16; o; o >>= 1) v = fminf(v, __shfl_xor_sync(0xffffffffu, v, o));
        if (lane == 0) out[(Y*WW + X)*N + nn] = v;
    }
}

// ---------------------------------------------------------------------------
extern "C" void kernel_launch(void* const* d_in, const int* in_sizes, int n_in,
                              void* d_out, int out_size) {
    const float* prev   = (const float*)d_in[0];
    const float* query  = (const float*)d_in[1];
    const int*   labels = (const int*)d_in[2];
    const int*   gt     = (const int*)d_in[3];
    float* out = (float*)d_out;
    int n = out_size / (HH*WW);

    kern_down<<<hH*hW*2/8, 256>>>(prev, query);   // 960 blocks
    dim3 gb(hW/PC, hH/PR);                        // 480 blocks
    kern_dist<<<gb, 256>>>();
    int blocks = HH*WW/8;
    switch (n) {
        case 1: kern_out<1><<<blocks,256>>>(labels, gt, out); break;
        case 2: kern_out<2><<<blocks,256>>>(labels, gt, out); break;
        case 3: kern_out<3><<<blocks,256>>>(labels, gt, out); break;
        case 4: kern_out<4><<<blocks,256>>>(labels, gt, out); break;
        case 5: kern_out<5><<<blocks,256>>>(labels, gt, out); break;
        case 6: kern_out<6><<<blocks,256>>>(labels, gt, out); break;
        case 7: kern_out<7><<<blocks,256>>>(labels, gt, out); break;
        default: kern_out<8><<<blocks,256>>>(labels, gt, out); break;
    }
}

// round 4
// speedup vs baseline: 1.0651x; 1.0651x over previous
#include <cuda_runtime.h>

// Fixed shapes
#define HH 96
#define WW 160
#define CC 100
#define hH 48
#define hW 80
#define MD 9
#define KD 19
#define K2 361
#define K2P 364          // padded stride for float4-aligned S rows

// int8 path
#define CP8 112          // channels padded to 112 int8 (7 x 16B chunks)
#define QSCALE 32.0f
#define QSCALE2_INV (1.0f/1024.0f)

// dist-kernel tiling
#define PR 2
#define PC 4
#define TROWS (PR + 2*MD)   // 20
#define TCOLS (PC + 2*MD)   // 22
#define TPITCH 28           // uint4 pitch -> conflict-free 8-lane LDS.128 phases
#define TPOS (TROWS*TCOLS)  // 440

// scratch (device globals; allocation is forbidden)
__device__ __align__(16) signed char g_xq[hH*hW*CP8];
__device__ __align__(16) signed char g_yq[hH*hW*CP8];
__device__ int g_sxq[hH*hW];
__device__ int g_syq[hH*hW];
__device__ __align__(16) float g_S[hH*hW*K2P];

// ---------------------------------------------------------------------------
// cp.async helpers (LDGSTS). src_size=0 -> zero fill (OOB handling).
// ---------------------------------------------------------------------------
__device__ __forceinline__ void cp_async16(void* dst, const void* src, int sz) {
    unsigned d = (unsigned)__cvta_generic_to_shared(dst);
    asm volatile("cp.async.ca.shared.global [%0], [%1], 16, %2;\n"
                 :: "r"(d), "l"(src), "r"(sz) : "memory");
}
__device__ __forceinline__ void cp_async4(void* dst, const void* src, int sz) {
    unsigned d = (unsigned)__cvta_generic_to_shared(dst);
    asm volatile("cp.async.ca.shared.global [%0], [%1], 4, %2;\n"
                 :: "r"(d), "l"(src), "r"(sz) : "memory");
}
__device__ __forceinline__ void cp_commit() { asm volatile("cp.async.commit_group;\n" ::: "memory"); }
template<int N> __device__ __forceinline__ void cp_wait() {
    asm volatile("cp.async.wait_group %0;\n" :: "n"(N) : "memory");
}

__device__ __forceinline__ void dp8(int& a, uint4 x, uint4 y) {
    a = __dp4a((int)x.x, (int)y.x, a);
    a = __dp4a((int)x.y, (int)y.y, a);
    a = __dp4a((int)x.z, (int)y.z, a);
    a = __dp4a((int)x.w, (int)y.w, a);
}

// ---------------------------------------------------------------------------
// Kernel A: 2x2 avg-pool + int8 quantize (scale 32) + per-pixel sum of squares.
// 128-thread blocks, one warp per (half-res pixel, tensor): 1920 blocks.
// ---------------------------------------------------------------------------
__global__ __launch_bounds__(128) void kern_down(const float* __restrict__ prev,
                                                 const float* __restrict__ query) {
    int w    = blockIdx.x * 4 + (threadIdx.x >> 5);
    int lane = threadIdx.x & 31;
    int pixel = w >> 1;
    int tsel  = w & 1;          // 0 -> prev/y, 1 -> query/x
    int r = pixel / hW, c = pixel - r*hW;
    int ch0 = lane * 4;

    const float* src = tsel ? query : prev;
    signed char* dst = tsel ? g_xq : g_yq;
    int* sums        = tsel ? g_sxq : g_syq;

    float4 v = make_float4(0.f,0.f,0.f,0.f);
    if (lane < 25) {
        int b = ((2*r)*WW + 2*c)*CC + ch0;
        float4 a0 = *(const float4*)&src[b];
        float4 a1 = *(const float4*)&src[b + CC];
        float4 a2 = *(const float4*)&src[b + WW*CC];
        float4 a3 = *(const float4*)&src[b + WW*CC + CC];
        v = make_float4(0.25f*(a0.x+a1.x+a2.x+a3.x), 0.25f*(a0.y+a1.y+a2.y+a3.y),
                        0.25f*(a0.z+a1.z+a2.z+a3.z), 0.25f*(a0.w+a1.w+a2.w+a3.w));
    }
    float vv[4] = {v.x, v.y, v.z, v.w};
    int q[4];
    int s = 0;
    #pragma unroll
    for (int t = 0; t < 4; t++) {
        int a = __float2int_rn(vv[t] * QSCALE);
        a = max(-127, min(127, a));
        q[t] = a;
        s += a*a;
    }
    if (lane < 28) {
        char4 cq = make_char4((char)q[0],(char)q[1],(char)q[2],(char)q[3]);
        *(char4*)&dst[pixel*CP8 + ch0] = cq;
    }
    s = __reduce_add_sync(0xffffffffu, s);
    if (lane == 0) sums[pixel] = s;

    cudaTriggerProgrammaticLaunchCompletion();
}

// ---------------------------------------------------------------------------
// Kernel B: local distances via int8 dp4a, cp.async ping-pong pipeline.
// Block = 2x4 pixel tile x 361 k. pix = tid&7, kgroup = tid>>3 (<=12 k each).
// Chunk pairs {0,1},{2,3},{4,5} then {6}+sums; next stage overlaps compute.
// ---------------------------------------------------------------------------
__global__ __launch_bounds__(256) void kern_dist() {
    __shared__ __align__(16) uint4 ysP[2][2][TROWS*TPITCH];
    __shared__ int sy_s[TPOS];

    int tid = threadIdx.x;
    int pix = tid & 7;
    int kg  = tid >> 3;          // 0..31
    int pr  = pix >> 2, pc = pix & 3;
    int r0 = blockIdx.y * PR, c0 = blockIdx.x * PC;
    int r = r0 + pr, c = c0 + pc;

    int soff[12];
    #pragma unroll
    for (int j = 0; j < 12; j++) {
        int k = kg + 32*j;
        int dy = k / KD;
        int dx = k - dy*KD;
        soff[j] = (pr + dy)*TPITCH + (pc + dx);
    }

    // precompute staging slots (each thread stages slot tid, and tid+256 if <440)
    int dsti[2], pos[2], sz[2];
    long srcoff[2];
    bool has[2] = {true, (tid + 256) < TPOS};
    #pragma unroll
    for (int s = 0; s < 2; s++) {
        int i = tid + 256*s;
        int ii = has[s] ? i : 0;
        int row = ii / TCOLS, col = ii - row*TCOLS;
        int gr = r0 - MD + row, gc = c0 - MD + col;
        bool ok = (unsigned)gr < hH && (unsigned)gc < hW;
        pos[s]  = ii;
        dsti[s] = row*TPITCH + col;
        srcoff[s] = ok ? (long)(gr*hW + gc)*CP8 : 0;
        sz[s] = ok ? 16 : 0;
    }

    // wait for kern_down's writes before touching g_* (PDL)
    cudaGridDependencySynchronize();

    const uint4* xg = reinterpret_cast<const uint4*>(&g_xq[(r*hW + c)*CP8]);

    int acc[12];
    #pragma unroll
    for (int j = 0; j < 12; j++) acc[j] = 0;

    #define STAGE_PAIR(base, A, B)                                         \
        _Pragma("unroll")                                                  \
        for (int s = 0; s < 2; s++) if (has[s]) {                          \
            const signed char* p = g_yq + srcoff[s] + (base)*16;           \
            cp_async16(&(A)[dsti[s]], p, sz[s]);                           \
            cp_async16(&(B)[dsti[s]], p + 16, sz[s]);                      \
        }

    #define COMP_PAIR(A, B, base)                                          \
        {                                                                  \
            uint4 xa = xg[base], xb = xg[(base)+1];                        \
            _Pragma("unroll")                                              \
            for (int j = 0; j < 11; j++) {                                 \
                uint4 ya = (A)[soff[j]];                                   \
                uint4 yb = (B)[soff[j]];                                   \
                dp8(acc[j], xa, ya); dp8(acc[j], xb, yb);                  \
            }                                                              \
            if (kg < 9) {                                                  \
                uint4 ya = (A)[soff[11]];                                  \
                uint4 yb = (B)[soff[11]];                                  \
                dp8(acc[11], xa, ya); dp8(acc[11], xb, yb);                \
            }                                                              \
        }

    STAGE_PAIR(0, ysP[0][0], ysP[0][1]); cp_commit();      // group 0
    STAGE_PAIR(2, ysP[1][0], ysP[1][1]); cp_commit();      // group 1
    cp_wait<1>(); __syncthreads();
    COMP_PAIR(ysP[0][0], ysP[0][1], 0);
    __syncthreads();
    STAGE_PAIR(4, ysP[0][0], ysP[0][1]); cp_commit();      // group 2
    cp_wait<1>(); __syncthreads();
    COMP_PAIR(ysP[1][0], ysP[1][1], 2);
    __syncthreads();
    // final stage: chunk 6 + neighbor sums into buffer 1
    #pragma unroll
    for (int s = 0; s < 2; s++) if (has[s]) {
        const signed char* p = g_yq + srcoff[s] + 96;
        cp_async16(&ysP[1][0][dsti[s]], p, sz[s]);
        const int* ps = g_syq + (srcoff[s] / CP8);
        cp_async4(&sy_s[pos[s]], ps, sz[s] ? 4 : 0);
    }
    cp_commit();                                           // group 3
    cp_wait<1>(); __syncthreads();
    COMP_PAIR(ysP[0][0], ysP[0][1], 4);
    __syncthreads();
    cp_wait<0>(); __syncthreads();
    {
        uint4 xa = xg[6];
        #pragma unroll
        for (int j = 0; j < 11; j++) { uint4 ya = ysP[1][0][soff[j]]; dp8(acc[j], xa, ya); }
        if (kg < 9)                  { uint4 ya = ysP[1][0][soff[11]]; dp8(acc[11], xa, ya); }
    }

    int sx = g_sxq[r*hW + c];
    float* Srow = &g_S[(r*hW + c)*K2P];
    #pragma unroll
    for (int j = 0; j < 12; j++) {
        int k = kg + 32*j;
        if (k < K2P) {
            float val = 1.0f;   // PAD / out-of-range -> saturated sigmoid
            if (k < K2) {
                int dy = k / KD, dx = k - dy*KD;
                int sr = r + dy - MD, sc = c + dx - MD;
                if (sr >= 0 && sr < hH && sc >= 0 && sc < hW) {
                    int di = sx + sy_s[(pr + dy)*TCOLS + (pc + dx)] - 2*acc[j];
                    float d = (float)di * QSCALE2_INV;
                    float e = __expf(-d);
                    val = (1.0f - e) / (1.0f + e);   // == (sigmoid(d)-0.5)*2
                }
            }
            Srow[k] = val;
        }
    }
    cudaTriggerProgrammaticLaunchCompletion();
}

// ---------------------------------------------------------------------------
// Kernel C: bilinear upsample (align_corners) + per-object masked min.
// Block = 8 consecutive output pixels (one warp each). Label staging + index
// math run BEFORE the PDL dependency sync (they only touch inputs).
// ---------------------------------------------------------------------------
#define LROWS KD           // 19
#define LCOLS (8 + 2*MD)   // 26
template<int N>
__global__ __launch_bounds__(256) void kern_out(const int* __restrict__ labels,
                                                const int* __restrict__ gt,
                                                float* __restrict__ out) {
    __shared__ int lab[LROWS*LCOLS];
    int tid  = threadIdx.x;
    int warp = tid >> 5;
    int lane = tid & 31;
    int wid = blockIdx.x * 8;
    int Y = wid / WW;
    int Xbase = wid - Y*WW;

    for (int i = tid; i < LROWS*LCOLS; i += 256) {
        int row = i / LCOLS, col = i - row*LCOLS;
        int gr = Y - MD + row, gc = Xbase - MD + col;
        lab[i] = (gr >= 0 && gr < HH && gc >= 0 && gc < WW) ? labels[gr*WW + gc] : -1;
    }

    int X = Xbase + warp;
    const float sH = (float)(47.0/95.0);
    const float sW = (float)(79.0/159.0);
    float pH = (float)Y * sH;
    float pW = (float)X * sW;
    int loH = (int)floorf(pH); if (loH > hH-2) loH = hH-2;
    int loW = (int)floorf(pW); if (loW > hW-2) loW = hW-2;
    float fH = pH - (float)loH;
    float fW = pW - (float)loW;
    float w00 = (1.f-fH)*(1.f-fW), w01 = (1.f-fH)*fW;
    float w10 = fH*(1.f-fW),       w11 = fH*fW;

    int gid[N];
    #pragma unroll
    for (int nn = 0; nn < N; nn++) gid[nn] = gt[nn];
    float mv[N];
    #pragma unroll
    for (int nn = 0; nn < N; nn++) mv[nn] = 1.0f;

    __syncthreads();                     // lab ready
    cudaGridDependencySynchronize();     // g_S ready (PDL)

    const float* S00 = &g_S[(loH*hW + loW)*K2P];
    const float* S01 = S00 + K2P;
    const float* S10 = S00 + hW*K2P;
    const float* S11 = S10 + K2P;

    #define DO4(kb, CHECK)                                                     \
        {                                                                      \
            float4 a  = *(const float4*)&S00[kb];                              \
            float4 b  = *(const float4*)&S01[kb];                              \
            float4 cc = *(const float4*)&S10[kb];                              \
            float4 dd = *(const float4*)&S11[kb];                              \
            float av[4] = {a.x,a.y,a.z,a.w};                                   \
            float bv[4] = {b.x,b.y,b.z,b.w};                                   \
            float cv[4] = {cc.x,cc.y,cc.z,cc.w};                               \
            float dv[4] = {dd.x,dd.y,dd.z,dd.w};                               \
            _Pragma("unroll")                                                  \
            for (int t = 0; t < 4; t++) {                                      \
                int k = (kb) + t;                                              \
                if (!(CHECK) || k < K2) {                                      \
                    int dy = k / KD, dx = k - dy*KD;                           \
                    int lbl = lab[dy*LCOLS + warp + dx];                       \
                    float dval = w00*av[t] + w01*bv[t] + w10*cv[t] + w11*dv[t];\
                    _Pragma("unroll")                                          \
                    for (int nn = 0; nn < N; nn++)                             \
                        if (lbl == gid[nn]) mv[nn] = fminf(mv[nn], dval);      \
                }                                                              \
            }                                                                  \
        }

    DO4(4*lane, 0);          // k 0..127   always valid
    DO4(128 + 4*lane, 0);    // k 128..255 always valid
    if (lane < 27) {         // k 256..360 (+pad)
        DO4(256 + 4*lane, 1);
    }

    #pragma unroll
    for (int nn = 0; nn < N; nn++) {
        float v = mv[nn];
        #pragma unroll
        for (int o = 16; o; o >>= 1) v = fminf(v, __shfl_xor_sync(0xffffffffu, v, o));
        if (lane == 0) out[(Y*WW + X)*N + nn] = v;
    }
}

// ---------------------------------------------------------------------------
template<int N>
static void launch_out_pdl(const int* labels, const int* gt, float* out) {
    cudaLaunchConfig_t cfg = {};
    cudaLaunchAttribute attr[1];
    attr[0].id = cudaLaunchAttributeProgrammaticStreamSerialization;
    attr[0].val.programmaticStreamSerializationAllowed = 1;
    cfg.gridDim  = dim3(HH*WW/8, 1, 1);
    cfg.blockDim = dim3(256, 1, 1);
    cfg.attrs = attr;
    cfg.numAttrs = 1;
    cfg.stream = 0;
    cudaLaunchKernelEx(&cfg, kern_out<N>, labels, gt, out);
}

extern "C" void kernel_launch(void* const* d_in, const int* in_sizes, int n_in,
                              void* d_out, int out_size) {
    const float* prev   = (const float*)d_in[0];
    const float* query  = (const float*)d_in[1];
    const int*   labels = (const int*)d_in[2];
    const int*   gt     = (const int*)d_in[3];
    float* out = (float*)d_out;
    int n = out_size / (HH*WW);

    kern_down<<<hH*hW*2/4, 128>>>(prev, query);   // 1920 blocks

    {   // kern_dist with PDL
        cudaLaunchConfig_t cfg = {};
        cudaLaunchAttribute attr[1];
        attr[0].id = cudaLaunchAttributeProgrammaticStreamSerialization;
        attr[0].val.programmaticStreamSerializationAllowed = 1;
        cfg.gridDim  = dim3(hW/PC, hH/PR, 1);     // 480 blocks
        cfg.blockDim = dim3(256, 1, 1);
        cfg.attrs = attr;
        cfg.numAttrs = 1;
        cfg.stream = 0;
        cudaLaunchKernelEx(&cfg, kern_dist);
    }

    switch (n) {
        case 1: launch_out_pdl<1>(labels, gt, out); break;
        case 2: launch_out_pdl<2>(labels, gt, out); break;
        case 3: launch_out_pdl<3>(labels, gt, out); break;
        case 4: launch_out_pdl<4>(labels, gt, out); break;
        case 5: launch_out_pdl<5>(labels, gt, out); break;
        case 6: launch_out_pdl<6>(labels, gt, out); break;
        case 7: launch_out_pdl<7>(labels, gt, out); break;
        default: launch_out_pdl<8>(labels, gt, out); break;
    }
}